// round 15
// baseline (speedup 1.0000x reference)
#include <cuda_runtime.h>
#include <cuda_bf16.h>
#include <math.h>

#define VOCAB 32000
#define EMB   32
#define HID   8
#define SEQ   64
#define BATCH 64
#define NROWS (SEQ*BATCH)   /* 4096 */
#define NTILES (VOCAB/8)    /* 4000 n8 tiles */
#define NTP    (NTILES/2)   /* 2000 tile-pairs */
#define NBLK_X (VOCAB/256)  /* 125 */
#define NGRP   (NROWS/64)   /* 64 row-groups */
#define LOG2E 1.4426950408889634f

typedef unsigned long long u64;

__device__ float g_A[2*SEQ*BATCH*10];
__device__ float g_h[NROWS*16];
__device__ float g_sum[NROWS];
__device__ int   g_cnt[NGRP];
// B fragments (bf16), per tile-PAIR per lane: uint4 {b0_e, b1_e, b0_o, b1_o}
__device__ unsigned g_B[NTP*128];        // 1 MB

__device__ __forceinline__ float tanh_fast(float x) {
    float y; asm("tanh.approx.f32 %0, %1;" : "=f"(y) : "f"(x)); return y;
}
__device__ __forceinline__ float ex2_fast(float x) {
    float y; asm("ex2.approx.f32 %0, %1;" : "=f"(y) : "f"(x)); return y;
}
__device__ __forceinline__ unsigned pack_bf16(float x, float y) {
    return (unsigned)__bfloat16_as_ushort(__float2bfloat16(x))
         | ((unsigned)__bfloat16_as_ushort(__float2bfloat16(y)) << 16);
}
__device__ __forceinline__ void split2(float2 v, unsigned& hi, unsigned& lo) {
    __nv_bfloat16 hx = __float2bfloat16(v.x);
    __nv_bfloat16 hy = __float2bfloat16(v.y);
    __nv_bfloat16 lx = __float2bfloat16(v.x - __bfloat162float(hx));
    __nv_bfloat16 ly = __float2bfloat16(v.y - __bfloat162float(hy));
    hi = (unsigned)__bfloat16_as_ushort(hx) | ((unsigned)__bfloat16_as_ushort(hy) << 16);
    lo = (unsigned)__bfloat16_as_ushort(lx) | ((unsigned)__bfloat16_as_ushort(ly) << 16);
}

__device__ __forceinline__ void mma_bf16(
    float& c0, float& c1, float& c2, float& c3,
    unsigned a0, unsigned a1, unsigned a2, unsigned a3,
    unsigned b0, unsigned b1)
{
    asm volatile(
        "mma.sync.aligned.m16n8k16.row.col.f32.bf16.bf16.f32 "
        "{%0,%1,%2,%3}, {%4,%5,%6,%7}, {%8,%9}, {%0,%1,%2,%3};"
        : "+f"(c0), "+f"(c1), "+f"(c2), "+f"(c3)
        : "r"(a0), "r"(a1), "r"(a2), "r"(a3), "r"(b0), "r"(b1));
}

__device__ __forceinline__ void build_a(int r0, int q, unsigned* ahi, unsigned* alo) {
    float2 x0 = *(const float2*)(g_h + (size_t)r0*16     + 2*q);
    float2 x1 = *(const float2*)(g_h + (size_t)(r0+8)*16 + 2*q);
    float2 x2 = *(const float2*)(g_h + (size_t)r0*16     + 2*q + 8);
    float2 x3 = *(const float2*)(g_h + (size_t)(r0+8)*16 + 2*q + 8);
    split2(x0, ahi[0], alo[0]);
    split2(x1, ahi[1], alo[1]);
    split2(x2, ahi[2], alo[2]);
    split2(x3, ahi[3], alo[3]);
}

// ---------------------------------------------------------------------------
// Kernel 0: embedding gather + input-projection precompute; zeroes g_sum/g_cnt.
// ---------------------------------------------------------------------------
__global__ __launch_bounds__(256) void k_pre(
    const int*   __restrict__ x,   const float* __restrict__ emb,
    const float* __restrict__ Wz1, const float* __restrict__ bz1,
    const float* __restrict__ Wr1, const float* __restrict__ br1,
    const float* __restrict__ Wh1, const float* __restrict__ bh1,
    const float* __restrict__ Wz2, const float* __restrict__ bz2,
    const float* __restrict__ Wr2, const float* __restrict__ br2,
    const float* __restrict__ Wh2, const float* __restrict__ bh2)
{
    int tid = threadIdx.x;
    if (blockIdx.x == 0 && tid < NGRP) g_cnt[tid] = 0;
    int pair = blockIdx.x*4 + (tid >> 6);   // 0..127
    int dir = pair >> 6, t = pair & 63, b = tid & 63;
    int gid = (dir*SEQ + t)*BATCH + b;
    if (gid < NROWS) g_sum[gid] = 0.f;

    const float* Wz = dir ? Wz2 : Wz1;
    const float* Wr = dir ? Wr2 : Wr1;
    const float* Wh = dir ? Wh2 : Wh1;
    float az = (dir ? bz2 : bz1)[0];
    float ar = (dir ? br2 : br1)[0];
    const float* bh = dir ? bh2 : bh1;
    float ah[8];
    #pragma unroll
    for (int j = 0; j < 8; j++) ah[j] = bh[j];

    int idx = x[t*BATCH + b];
    const float* e = emb + (size_t)idx * EMB;
    float ev[32];
    #pragma unroll
    for (int k = 0; k < 8; k++) {
        float4 v4 = ((const float4*)e)[k];
        ev[4*k+0] = v4.x; ev[4*k+1] = v4.y; ev[4*k+2] = v4.z; ev[4*k+3] = v4.w;
    }
    #pragma unroll
    for (int k = 0; k < 32; k++) {
        float evk = ev[k];
        az += evk * Wz[8 + k];
        ar += evk * Wr[8 + k];
        #pragma unroll
        for (int j = 0; j < 8; j++) ah[j] += evk * Wh[(8 + k)*8 + j];
    }
    float* Ab = g_A + (size_t)((dir*SEQ + t)*10)*BATCH + b;
    Ab[0] = az;
    Ab[BATCH] = ar;
    #pragma unroll
    for (int j = 0; j < 8; j++) Ab[(2 + j)*BATCH] = ah[j];
}

// ---------------------------------------------------------------------------
// Kernel 1: block 0 runs the serial GRU; blocks 1..125 build the B image.
// ---------------------------------------------------------------------------
__global__ __launch_bounds__(256) void k_gru_prep(
    const float* __restrict__ Wout,
    const float* __restrict__ Wz1, const float* __restrict__ Wr1, const float* __restrict__ Wh1,
    const float* __restrict__ Wz2, const float* __restrict__ Wr2, const float* __restrict__ Wh2)
{
    int bx = blockIdx.x, tid = threadIdx.x;
    if (bx > 0) {
        int v = (bx - 1)*256 + tid;   // 0..31999
        int g = v & 7, half = (v >> 3) & 1, tp = v >> 4;
        unsigned* bp = g_B + (size_t)tp*128 + half*2;
        #pragma unroll
        for (int q = 0; q < 4; q++) {
            float w0 = Wout[(size_t)(2*q)  *VOCAB + v];
            float w1 = Wout[(size_t)(2*q+1)*VOCAB + v];
            float w2 = Wout[(size_t)(2*q+8)*VOCAB + v];
            float w3 = Wout[(size_t)(2*q+9)*VOCAB + v];
            bp[(g*4+q)*4 + 0] = pack_bf16(w0, w1);
            bp[(g*4+q)*4 + 1] = pack_bf16(w2, w3);
        }
        return;
    }
    if (tid >= 128) return;
    int dir = tid >> 6, b = tid & 63;
    const float* Wz = dir ? Wz2 : Wz1;
    const float* Wr = dir ? Wr2 : Wr1;
    const float* Wh = dir ? Wh2 : Wh1;

    float wz[8], wr[8], wh[64];
    #pragma unroll
    for (int i = 0; i < 8; i++) { wz[i] = Wz[i]; wr[i] = Wr[i]; }
    #pragma unroll
    for (int i = 0; i < 64; i++) wh[i] = Wh[i];

    float h[8];
    #pragma unroll
    for (int j = 0; j < 8; j++) h[j] = 0.f;

    for (int step = 0; step < SEQ; ++step) {
        int time = dir ? (SEQ - 1 - step) : step;

        float* gh = g_h + (size_t)(time*BATCH + b)*16 + dir*8;
        ((float4*)gh)[0] = make_float4(h[0], h[1], h[2], h[3]);
        ((float4*)gh)[1] = make_float4(h[4], h[5], h[6], h[7]);

        const float* A = g_A + (size_t)((dir*SEQ + time)*10)*BATCH + b;
        float zi = A[0], ri = A[BATCH];
        #pragma unroll
        for (int i = 0; i < 8; i++) { zi += h[i]*wz[i]; ri += h[i]*wr[i]; }
        float z = 1.f / (1.f + __expf(-zi));
        float r = 1.f / (1.f + __expf(-ri));
        float hc[8];
        #pragma unroll
        for (int j = 0; j < 8; j++) {
            float s = A[(2 + j)*BATCH];
            #pragma unroll
            for (int i = 0; i < 8; i++) s += (r*h[i]) * wh[i*8 + j];
            hc[j] = tanh_fast(s);
        }
        #pragma unroll
        for (int j = 0; j < 8; j++) h[j] += z * (hc[j] - h[j]);
    }
}

// ---------------------------------------------------------------------------
// Fused logits kernel. Phase 1: MMA -> expsum -> atomicAdd + group counter.
// Spin until the row-group's 125 blocks have summed. Phase 2: recompute MMA,
// add bias - lse, transposed coalesced store (R13 single-buffer epilogue).
// ---------------------------------------------------------------------------
__global__ __launch_bounds__(256) void k_mma_fused(
    const float* __restrict__ bout, float* __restrict__ out)
{
    __shared__ __align__(16) float sb[256];
    __shared__ float snls[64];
    __shared__ __align__(16) uint4 tsm[8][16*8];   // 16 KB

    int tid = threadIdx.x, lane = tid & 31, warp = tid >> 5;
    int mw = warp & 3, nw = warp >> 2;
    int n0 = blockIdx.x*256;
    int ygrp = blockIdx.y;
    sb[tid] = bout[n0 + tid];
    __syncthreads();

    int q = lane & 3, g = lane >> 2;
    int rowbase = ygrp*64 + mw*16;
    int r0 = rowbase + g;
    unsigned ahi[4], alo[4];
    build_a(r0, q, ahi, alo);

    const unsigned* Bp = g_B + ((size_t)(n0 >> 4) + nw*8)*128;
    const float* sbw = sb + nw*128;

    // ---- phase 1: exp-sum (logits with unscaled bias; scale by log2e at ex2)
    float accA = 0.f, accB = 0.f;
    #pragma unroll
    for (int tp = 0; tp < 8; tp++) {
        uint4 B = *(const uint4*)(Bp + tp*128 + lane*4);
        float2 bb0 = *(const float2*)(sbw + tp*16 + 2*q);
        float c0 = bb0.x, c1 = bb0.y, c2 = bb0.x, c3 = bb0.y;
        mma_bf16(c0,c1,c2,c3, ahi[0],ahi[1],ahi[2],ahi[3], B.x,B.y);
        mma_bf16(c0,c1,c2,c3, alo[0],alo[1],alo[2],alo[3], B.x,B.y);
        accA += ex2_fast(LOG2E*c0) + ex2_fast(LOG2E*c1);
        accB += ex2_fast(LOG2E*c2) + ex2_fast(LOG2E*c3);
        float2 bb1 = *(const float2*)(sbw + tp*16 + 8 + 2*q);
        float d0 = bb1.x, d1 = bb1.y, d2 = bb1.x, d3 = bb1.y;
        mma_bf16(d0,d1,d2,d3, ahi[0],ahi[1],ahi[2],ahi[3], B.z,B.w);
        mma_bf16(d0,d1,d2,d3, alo[0],alo[1],alo[2],alo[3], B.z,B.w);
        accA += ex2_fast(LOG2E*d0) + ex2_fast(LOG2E*d1);
        accB += ex2_fast(LOG2E*d2) + ex2_fast(LOG2E*d3);
    }
    accA += __shfl_xor_sync(0xffffffffu, accA, 1);
    accA += __shfl_xor_sync(0xffffffffu, accA, 2);
    accB += __shfl_xor_sync(0xffffffffu, accB, 1);
    accB += __shfl_xor_sync(0xffffffffu, accB, 2);
    if (q == 0) {
        atomicAdd(&g_sum[r0],     accA);
        atomicAdd(&g_sum[r0 + 8], accB);
    }
    __syncthreads();

    // ---- cross-block sync for this row-group
    if (tid == 0) {
        __threadfence();
        atomicAdd(&g_cnt[ygrp], 1);
        while (*(volatile int*)&g_cnt[ygrp] < NBLK_X) __nanosleep(200);
    }
    __syncthreads();
    __threadfence();
    if (tid < 64) {
        float s;
        asm volatile("ld.global.cg.f32 %0, [%1];" : "=f"(s) : "l"(&g_sum[ygrp*64 + tid]));
        snls[tid] = -__logf(s);
    }
    __syncthreads();
    float nlsA = snls[mw*16 + g], nlsB = snls[mw*16 + g + 8];

    // ---- phase 2: recompute + transposed store
    float* tw = (float*)tsm[warp];
    int colbase = n0 + nw*128;
    int h = q & 1;

    #pragma unroll
    for (int G = 0; G < 4; G++) {
        #pragma unroll
        for (int tpp = 0; tpp < 2; tpp++) {
            int tp = G*2 + tpp;
            uint4 B = *(const uint4*)(Bp + tp*128 + lane*4);
            #pragma unroll
            for (int hf = 0; hf < 2; hf++) {
                int t = tp*2 + hf;
                int tt = tpp*2 + hf;
                unsigned b0 = hf ? B.z : B.x;
                unsigned b1 = hf ? B.w : B.y;
                float2 bb = *(const float2*)(sbw + t*8 + 2*q);
                float c0 = bb.x, c1 = bb.y, c2 = bb.x, c3 = bb.y;
                mma_bf16(c0,c1,c2,c3, ahi[0],ahi[1],ahi[2],ahi[3], b0,b1);
                mma_bf16(c0,c1,c2,c3, alo[0],alo[1],alo[2],alo[3], b0,b1);
                int Gl = tt*2 + (q >> 1);
                int pa = Gl ^ (g & 7);
                int pb = Gl ^ ((g + 8) & 7);
                *(float2*)(tw + (g*8 + pa)*4 + h*2)     = make_float2(c0 + nlsA, c1 + nlsA);
                *(float2*)(tw + ((g+8)*8 + pb)*4 + h*2) = make_float2(c2 + nlsB, c3 + nlsB);
            }
        }
        __syncwarp();
        #pragma unroll
        for (int i = 0; i < 4; i++) {
            int r = i*4 + (lane >> 3);
            int k = lane & 7;
            int p = k ^ (r & 7);
            uint4 vv = tsm[warp][r*8 + p];
            float* pd = out + (size_t)(rowbase + r)*VOCAB + colbase + G*32 + k*4;
            asm volatile("st.global.cs.v4.b32 [%0], {%1, %2, %3, %4};"
                         :: "l"(pd), "r"(vv.x), "r"(vv.y), "r"(vv.z), "r"(vv.w) : "memory");
        }
        __syncwarp();
    }
}

// ---------------------------------------------------------------------------
extern "C" void kernel_launch(void* const* d_in, const int* in_sizes, int n_in,
                              void* d_out, int out_size)
{
    const int*   x    = (const int*)  d_in[0];
    const float* emb  = (const float*)d_in[1];
    const float* Wz1  = (const float*)d_in[2];  const float* bz1 = (const float*)d_in[3];
    const float* Wr1  = (const float*)d_in[4];  const float* br1 = (const float*)d_in[5];
    const float* Wh1  = (const float*)d_in[6];  const float* bh1 = (const float*)d_in[7];
    const float* Wz2  = (const float*)d_in[8];  const float* bz2 = (const float*)d_in[9];
    const float* Wr2  = (const float*)d_in[10]; const float* br2 = (const float*)d_in[11];
    const float* Wh2  = (const float*)d_in[12]; const float* bh2 = (const float*)d_in[13];
    const float* Wout = (const float*)d_in[14]; const float* bout= (const float*)d_in[15];
    float* out = (float*)d_out;

    k_pre<<<32, 256>>>(x, emb, Wz1, bz1, Wr1, br1, Wh1, bh1,
                       Wz2, bz2, Wr2, br2, Wh2, bh2);
    k_gru_prep<<<126, 256>>>(Wout, Wz1, Wr1, Wh1, Wz2, Wr2, Wh2);
    k_mma_fused<<<dim3(NBLK_X, NGRP), 256>>>(bout, out);
}

// round 16
// speedup vs baseline: 1.2530x; 1.2530x over previous
#include <cuda_runtime.h>
#include <cuda_bf16.h>
#include <math.h>

#define VOCAB 32000
#define EMB   32
#define HID   8
#define SEQ   64
#define BATCH 64
#define NROWS (SEQ*BATCH)   /* 4096 */
#define NTILES (VOCAB/8)    /* 4000 n8 tiles */
#define NTP    (NTILES/2)   /* 2000 tile-pairs */
#define LOG2E 1.4426950408889634f

typedef unsigned long long u64;

__device__ float g_A[2*SEQ*BATCH*10];
__device__ float g_h[NROWS*16];
__device__ float g_sum[NROWS];
__device__ int   g_pre_done;             // zero-init; self-resetting
// B fragments (bf16), per tile-PAIR per lane: uint4 {b0_e, b1_e, b0_o, b1_o}
__device__ unsigned g_B[NTP*128];        // 1 MB

__device__ __forceinline__ float tanh_fast(float x) {
    float y; asm("tanh.approx.f32 %0, %1;" : "=f"(y) : "f"(x)); return y;
}
__device__ __forceinline__ float ex2_fast(float x) {
    float y; asm("ex2.approx.f32 %0, %1;" : "=f"(y) : "f"(x)); return y;
}
__device__ __forceinline__ unsigned pack_bf16(float x, float y) {
    return (unsigned)__bfloat16_as_ushort(__float2bfloat16(x))
         | ((unsigned)__bfloat16_as_ushort(__float2bfloat16(y)) << 16);
}
__device__ __forceinline__ void split2(float2 v, unsigned& hi, unsigned& lo) {
    __nv_bfloat16 hx = __float2bfloat16(v.x);
    __nv_bfloat16 hy = __float2bfloat16(v.y);
    __nv_bfloat16 lx = __float2bfloat16(v.x - __bfloat162float(hx));
    __nv_bfloat16 ly = __float2bfloat16(v.y - __bfloat162float(hy));
    hi = (unsigned)__bfloat16_as_ushort(hx) | ((unsigned)__bfloat16_as_ushort(hy) << 16);
    lo = (unsigned)__bfloat16_as_ushort(lx) | ((unsigned)__bfloat16_as_ushort(ly) << 16);
}

__device__ __forceinline__ void mma_bf16(
    float& c0, float& c1, float& c2, float& c3,
    unsigned a0, unsigned a1, unsigned a2, unsigned a3,
    unsigned b0, unsigned b1)
{
    asm volatile(
        "mma.sync.aligned.m16n8k16.row.col.f32.bf16.bf16.f32 "
        "{%0,%1,%2,%3}, {%4,%5,%6,%7}, {%8,%9}, {%0,%1,%2,%3};"
        : "+f"(c0), "+f"(c1), "+f"(c2), "+f"(c3)
        : "r"(a0), "r"(a1), "r"(a2), "r"(a3), "r"(b0), "r"(b1));
}

__device__ __forceinline__ void build_a(int r0, int q, float scale,
                                        unsigned* ahi, unsigned* alo) {
    float2 x0 = *(const float2*)(g_h + (size_t)r0*16     + 2*q);
    float2 x1 = *(const float2*)(g_h + (size_t)(r0+8)*16 + 2*q);
    float2 x2 = *(const float2*)(g_h + (size_t)r0*16     + 2*q + 8);
    float2 x3 = *(const float2*)(g_h + (size_t)(r0+8)*16 + 2*q + 8);
    x0.x *= scale; x0.y *= scale; x1.x *= scale; x1.y *= scale;
    x2.x *= scale; x2.y *= scale; x3.x *= scale; x3.y *= scale;
    split2(x0, ahi[0], alo[0]);
    split2(x1, ahi[1], alo[1]);
    split2(x2, ahi[2], alo[2]);
    split2(x3, ahi[3], alo[3]);
}

// ---------------------------------------------------------------------------
// Front kernel — ONE launch, three roles:
//   block 0        : serial GRU (spins until the 32 pre-blocks signal)
//   blocks 1..125  : B fragment image build
//   blocks 126..157: embedding + input-projection precompute (g_A), zero g_sum
// All 158 blocks fit in one wave -> the spin's producers are co-resident.
// ---------------------------------------------------------------------------
__global__ __launch_bounds__(256) void k_front(
    const float* __restrict__ Wout,
    const int*   __restrict__ x,   const float* __restrict__ emb,
    const float* __restrict__ Wz1, const float* __restrict__ bz1,
    const float* __restrict__ Wr1, const float* __restrict__ br1,
    const float* __restrict__ Wh1, const float* __restrict__ bh1,
    const float* __restrict__ Wz2, const float* __restrict__ bz2,
    const float* __restrict__ Wr2, const float* __restrict__ br2,
    const float* __restrict__ Wh2, const float* __restrict__ bh2)
{
    int bx = blockIdx.x, tid = threadIdx.x;

    if (bx >= 1 && bx <= 125) {
        // ---- B image build ----
        int v = (bx - 1)*256 + tid;   // 0..31999
        int g = v & 7, half = (v >> 3) & 1, tp = v >> 4;
        unsigned* bp = g_B + (size_t)tp*128 + half*2;
        #pragma unroll
        for (int q = 0; q < 4; q++) {
            float w0 = Wout[(size_t)(2*q)  *VOCAB + v];
            float w1 = Wout[(size_t)(2*q+1)*VOCAB + v];
            float w2 = Wout[(size_t)(2*q+8)*VOCAB + v];
            float w3 = Wout[(size_t)(2*q+9)*VOCAB + v];
            bp[(g*4+q)*4 + 0] = pack_bf16(w0, w1);
            bp[(g*4+q)*4 + 1] = pack_bf16(w2, w3);
        }
        return;
    }

    if (bx >= 126) {
        // ---- pre path ----
        int pair = (bx - 126)*4 + (tid >> 6);   // 0..127
        int dir = pair >> 6, t = pair & 63, b = tid & 63;
        int gid = (dir*SEQ + t)*BATCH + b;
        if (gid < NROWS) g_sum[gid] = 0.f;

        const float* Wz = dir ? Wz2 : Wz1;
        const float* Wr = dir ? Wr2 : Wr1;
        const float* Wh = dir ? Wh2 : Wh1;
        float az = (dir ? bz2 : bz1)[0];
        float ar = (dir ? br2 : br1)[0];
        const float* bh = dir ? bh2 : bh1;
        float ah[8];
        #pragma unroll
        for (int j = 0; j < 8; j++) ah[j] = bh[j];

        int idx = x[t*BATCH + b];
        const float* e = emb + (size_t)idx * EMB;
        float ev[32];
        #pragma unroll
        for (int k = 0; k < 8; k++) {
            float4 v4 = ((const float4*)e)[k];
            ev[4*k+0] = v4.x; ev[4*k+1] = v4.y; ev[4*k+2] = v4.z; ev[4*k+3] = v4.w;
        }
        #pragma unroll
        for (int k = 0; k < 32; k++) {
            float evk = ev[k];
            az += evk * Wz[8 + k];
            ar += evk * Wr[8 + k];
            #pragma unroll
            for (int j = 0; j < 8; j++) ah[j] += evk * Wh[(8 + k)*8 + j];
        }
        float* Ab = g_A + (size_t)((dir*SEQ + t)*10)*BATCH + b;
        Ab[0] = az;
        Ab[BATCH] = ar;
        #pragma unroll
        for (int j = 0; j < 8; j++) Ab[(2 + j)*BATCH] = ah[j];

        __threadfence();
        __syncthreads();
        if (tid == 0) atomicAdd(&g_pre_done, 1);
        return;
    }

    // ---- block 0: serial GRU (waits for the 32 pre-blocks) ----
    if (tid == 0) {
        while (*(volatile int*)&g_pre_done < 32) __nanosleep(100);
        g_pre_done = 0;                 // reset for next graph replay
    }
    __syncthreads();
    __threadfence();
    if (tid >= 128) return;

    int dir = tid >> 6, b = tid & 63;
    const float* Wz = dir ? Wz2 : Wz1;
    const float* Wr = dir ? Wr2 : Wr1;
    const float* Wh = dir ? Wh2 : Wh1;

    float wz[8], wr[8], wh[64];
    #pragma unroll
    for (int i = 0; i < 8; i++) { wz[i] = Wz[i]; wr[i] = Wr[i]; }
    #pragma unroll
    for (int i = 0; i < 64; i++) wh[i] = Wh[i];

    float h[8];
    #pragma unroll
    for (int j = 0; j < 8; j++) h[j] = 0.f;

    for (int step = 0; step < SEQ; ++step) {
        int time = dir ? (SEQ - 1 - step) : step;

        float* gh = g_h + (size_t)(time*BATCH + b)*16 + dir*8;
        ((float4*)gh)[0] = make_float4(h[0], h[1], h[2], h[3]);
        ((float4*)gh)[1] = make_float4(h[4], h[5], h[6], h[7]);

        const float* A = g_A + (size_t)((dir*SEQ + time)*10)*BATCH + b;
        float zi = A[0], ri = A[BATCH];
        #pragma unroll
        for (int i = 0; i < 8; i++) { zi += h[i]*wz[i]; ri += h[i]*wr[i]; }
        float z = 1.f / (1.f + __expf(-zi));
        float r = 1.f / (1.f + __expf(-ri));
        float hc[8];
        #pragma unroll
        for (int j = 0; j < 8; j++) {
            float s = A[(2 + j)*BATCH];
            #pragma unroll
            for (int i = 0; i < 8; i++) s += (r*h[i]) * wh[i*8 + j];
            hc[j] = tanh_fast(s);
        }
        #pragma unroll
        for (int j = 0; j < 8; j++) h[j] += z * (hc[j] - h[j]);
    }
}

// ---------------------------------------------------------------------------
// Sum pass — R13 measured form (A and bias pre-scaled by log2e; 2 MMAs/tile).
// ---------------------------------------------------------------------------
__global__ __launch_bounds__(256) void k_mma_sum(const float* __restrict__ bout)
{
    __shared__ __align__(16) float sb[256];
    int tid = threadIdx.x, lane = tid & 31, warp = tid >> 5;
    int mw = warp & 3, nw = warp >> 2;
    int n0 = blockIdx.x*256;
    sb[tid] = bout[n0 + tid] * LOG2E;
    __syncthreads();

    int q = lane & 3, g = lane >> 2;
    int r0 = blockIdx.y*64 + mw*16 + g;
    unsigned ahi[4], alo[4];
    build_a(r0, q, LOG2E, ahi, alo);

    const unsigned* Bp = g_B + ((size_t)(n0 >> 4) + nw*8)*128;
    const float* sbw = sb + nw*128;
    float accA = 0.f, accB = 0.f;

    #pragma unroll
    for (int tp = 0; tp < 8; tp++) {
        uint4 B = *(const uint4*)(Bp + tp*128 + lane*4);
        float2 bb0 = *(const float2*)(sbw + tp*16 + 2*q);
        float c0 = bb0.x, c1 = bb0.y, c2 = bb0.x, c3 = bb0.y;
        mma_bf16(c0,c1,c2,c3, ahi[0],ahi[1],ahi[2],ahi[3], B.x,B.y);
        mma_bf16(c0,c1,c2,c3, alo[0],alo[1],alo[2],alo[3], B.x,B.y);
        accA += ex2_fast(c0) + ex2_fast(c1);
        accB += ex2_fast(c2) + ex2_fast(c3);
        float2 bb1 = *(const float2*)(sbw + tp*16 + 8 + 2*q);
        float d0 = bb1.x, d1 = bb1.y, d2 = bb1.x, d3 = bb1.y;
        mma_bf16(d0,d1,d2,d3, ahi[0],ahi[1],ahi[2],ahi[3], B.z,B.w);
        mma_bf16(d0,d1,d2,d3, alo[0],alo[1],alo[2],alo[3], B.z,B.w);
        accA += ex2_fast(d0) + ex2_fast(d1);
        accB += ex2_fast(d2) + ex2_fast(d3);
    }
    accA += __shfl_xor_sync(0xffffffffu, accA, 1);
    accA += __shfl_xor_sync(0xffffffffu, accA, 2);
    accB += __shfl_xor_sync(0xffffffffu, accB, 1);
    accB += __shfl_xor_sync(0xffffffffu, accB, 2);
    if (q == 0) {
        atomicAdd(&g_sum[r0],     accA);
        atomicAdd(&g_sum[r0 + 8], accB);
    }
}

// ---------------------------------------------------------------------------
// Write pass — R13 single-buffer transposed epilogue (92.1us measured).
// ---------------------------------------------------------------------------
__global__ __launch_bounds__(256) void k_mma_write(
    const float* __restrict__ bout, float* __restrict__ out)
{
    __shared__ __align__(16) float sb[256];
    __shared__ float snls[64];
    __shared__ __align__(16) uint4 tsm[8][16*8];   // 16 KB

    int tid = threadIdx.x, lane = tid & 31, warp = tid >> 5;
    int mw = warp & 3, nw = warp >> 2;
    int n0 = blockIdx.x*256;
    sb[tid] = bout[n0 + tid];
    if (tid < 64) snls[tid] = -__logf(g_sum[blockIdx.y*64 + tid]);
    __syncthreads();

    int q = lane & 3, g = lane >> 2;
    int rowbase = blockIdx.y*64 + mw*16;
    int r0 = rowbase + g;
    unsigned ahi[4], alo[4];
    build_a(r0, q, 1.0f, ahi, alo);
    float nlsA = snls[mw*16 + g], nlsB = snls[mw*16 + g + 8];

    const unsigned* Bp = g_B + ((size_t)(n0 >> 4) + nw*8)*128;
    const float* sbw = sb + nw*128;
    float* tw = (float*)tsm[warp];
    int colbase = n0 + nw*128;
    int h = q & 1;

    #pragma unroll
    for (int G = 0; G < 4; G++) {
        #pragma unroll
        for (int tpp = 0; tpp < 2; tpp++) {
            int tp = G*2 + tpp;
            uint4 B = *(const uint4*)(Bp + tp*128 + lane*4);
            #pragma unroll
            for (int hf = 0; hf < 2; hf++) {
                int t = tp*2 + hf;
                int tt = tpp*2 + hf;
                unsigned b0 = hf ? B.z : B.x;
                unsigned b1 = hf ? B.w : B.y;
                float2 bb = *(const float2*)(sbw + t*8 + 2*q);
                float c0 = bb.x, c1 = bb.y, c2 = bb.x, c3 = bb.y;
                mma_bf16(c0,c1,c2,c3, ahi[0],ahi[1],ahi[2],ahi[3], b0,b1);
                mma_bf16(c0,c1,c2,c3, alo[0],alo[1],alo[2],alo[3], b0,b1);
                int Gl = tt*2 + (q >> 1);
                int pa = Gl ^ (g & 7);
                int pb = Gl ^ ((g + 8) & 7);
                *(float2*)(tw + (g*8 + pa)*4 + h*2)     = make_float2(c0 + nlsA, c1 + nlsA);
                *(float2*)(tw + ((g+8)*8 + pb)*4 + h*2) = make_float2(c2 + nlsB, c3 + nlsB);
            }
        }
        __syncwarp();
        #pragma unroll
        for (int i = 0; i < 4; i++) {
            int r = i*4 + (lane >> 3);
            int k = lane & 7;
            int p = k ^ (r & 7);
            uint4 vv = tsm[warp][r*8 + p];
            float* pd = out + (size_t)(rowbase + r)*VOCAB + colbase + G*32 + k*4;
            asm volatile("st.global.cs.v4.b32 [%0], {%1, %2, %3, %4};"
                         :: "l"(pd), "r"(vv.x), "r"(vv.y), "r"(vv.z), "r"(vv.w) : "memory");
        }
        __syncwarp();
    }
}

// ---------------------------------------------------------------------------
extern "C" void kernel_launch(void* const* d_in, const int* in_sizes, int n_in,
                              void* d_out, int out_size)
{
    const int*   x    = (const int*)  d_in[0];
    const float* emb  = (const float*)d_in[1];
    const float* Wz1  = (const float*)d_in[2];  const float* bz1 = (const float*)d_in[3];
    const float* Wr1  = (const float*)d_in[4];  const float* br1 = (const float*)d_in[5];
    const float* Wh1  = (const float*)d_in[6];  const float* bh1 = (const float*)d_in[7];
    const float* Wz2  = (const float*)d_in[8];  const float* bz2 = (const float*)d_in[9];
    const float* Wr2  = (const float*)d_in[10]; const float* br2 = (const float*)d_in[11];
    const float* Wh2  = (const float*)d_in[12]; const float* bh2 = (const float*)d_in[13];
    const float* Wout = (const float*)d_in[14]; const float* bout= (const float*)d_in[15];
    float* out = (float*)d_out;

    k_front<<<158, 256>>>(Wout, x, emb, Wz1, bz1, Wr1, br1, Wh1, bh1,
                          Wz2, bz2, Wr2, br2, Wh2, bh2);
    k_mma_sum  <<<dim3(VOCAB/256, NROWS/64), 256>>>(bout);
    k_mma_write<<<dim3(VOCAB/256, NROWS/64), 256>>>(bout, out);
}

// round 17
// speedup vs baseline: 1.3996x; 1.1170x over previous
#include <cuda_runtime.h>
#include <cuda_bf16.h>
#include <math.h>

#define VOCAB 32000
#define EMB   32
#define HID   8
#define SEQ   64
#define BATCH 64
#define NROWS (SEQ*BATCH)   /* 4096 */
#define NTILES (VOCAB/8)    /* 4000 n8 tiles */
#define NTP    (NTILES/2)   /* 2000 tile-pairs */
#define LOG2E 1.4426950408889634f

typedef unsigned long long u64;

__device__ float g_A[2*SEQ*BATCH*10];
__device__ float g_h[NROWS*16];
__device__ float g_sum[NROWS];
__device__ int   g_pre_flag[32];         // zero-init; self-resetting
// B fragments (bf16), per tile-PAIR per lane: uint4 {b0_e, b1_e, b0_o, b1_o}
__device__ unsigned g_B[NTP*128];        // 1 MB

__device__ __forceinline__ float tanh_fast(float x) {
    float y; asm("tanh.approx.f32 %0, %1;" : "=f"(y) : "f"(x)); return y;
}
__device__ __forceinline__ float sigmoid_fast(float x) {
    return fmaf(tanh_fast(0.5f*x), 0.5f, 0.5f);
}
__device__ __forceinline__ float ex2_fast(float x) {
    float y; asm("ex2.approx.f32 %0, %1;" : "=f"(y) : "f"(x)); return y;
}
__device__ __forceinline__ unsigned pack_bf16(float x, float y) {
    return (unsigned)__bfloat16_as_ushort(__float2bfloat16(x))
         | ((unsigned)__bfloat16_as_ushort(__float2bfloat16(y)) << 16);
}
__device__ __forceinline__ void split2(float2 v, unsigned& hi, unsigned& lo) {
    __nv_bfloat16 hx = __float2bfloat16(v.x);
    __nv_bfloat16 hy = __float2bfloat16(v.y);
    __nv_bfloat16 lx = __float2bfloat16(v.x - __bfloat162float(hx));
    __nv_bfloat16 ly = __float2bfloat16(v.y - __bfloat162float(hy));
    hi = (unsigned)__bfloat16_as_ushort(hx) | ((unsigned)__bfloat16_as_ushort(hy) << 16);
    lo = (unsigned)__bfloat16_as_ushort(lx) | ((unsigned)__bfloat16_as_ushort(ly) << 16);
}

__device__ __forceinline__ void mma_bf16(
    float& c0, float& c1, float& c2, float& c3,
    unsigned a0, unsigned a1, unsigned a2, unsigned a3,
    unsigned b0, unsigned b1)
{
    asm volatile(
        "mma.sync.aligned.m16n8k16.row.col.f32.bf16.bf16.f32 "
        "{%0,%1,%2,%3}, {%4,%5,%6,%7}, {%8,%9}, {%0,%1,%2,%3};"
        : "+f"(c0), "+f"(c1), "+f"(c2), "+f"(c3)
        : "r"(a0), "r"(a1), "r"(a2), "r"(a3), "r"(b0), "r"(b1));
}

__device__ __forceinline__ void build_a(int r0, int q, float scale,
                                        unsigned* ahi, unsigned* alo) {
    float2 x0 = *(const float2*)(g_h + (size_t)r0*16     + 2*q);
    float2 x1 = *(const float2*)(g_h + (size_t)(r0+8)*16 + 2*q);
    float2 x2 = *(const float2*)(g_h + (size_t)r0*16     + 2*q + 8);
    float2 x3 = *(const float2*)(g_h + (size_t)(r0+8)*16 + 2*q + 8);
    x0.x *= scale; x0.y *= scale; x1.x *= scale; x1.y *= scale;
    x2.x *= scale; x2.y *= scale; x3.x *= scale; x3.y *= scale;
    split2(x0, ahi[0], alo[0]);
    split2(x1, ahi[1], alo[1]);
    split2(x2, ahi[2], alo[2]);
    split2(x3, ahi[3], alo[3]);
}

// ---------------------------------------------------------------------------
// Front kernel — ONE launch, three roles:
//   block 0        : serial GRU with per-group flag waits + A prefetch
//   blocks 1..125  : B fragment image build
//   blocks 126..157: embedding + input-projection precompute (g_A), zero g_sum;
//                    each releases g_pre_flag[bx-126] covering its 4 pairs.
// ---------------------------------------------------------------------------
__global__ __launch_bounds__(256) void k_front(
    const float* __restrict__ Wout,
    const int*   __restrict__ x,   const float* __restrict__ emb,
    const float* __restrict__ Wz1, const float* __restrict__ bz1,
    const float* __restrict__ Wr1, const float* __restrict__ br1,
    const float* __restrict__ Wh1, const float* __restrict__ bh1,
    const float* __restrict__ Wz2, const float* __restrict__ bz2,
    const float* __restrict__ Wr2, const float* __restrict__ br2,
    const float* __restrict__ Wh2, const float* __restrict__ bh2)
{
    int bx = blockIdx.x, tid = threadIdx.x;

    if (bx >= 1 && bx <= 125) {
        // ---- B image build ----
        int v = (bx - 1)*256 + tid;   // 0..31999
        int g = v & 7, half = (v >> 3) & 1, tp = v >> 4;
        unsigned* bp = g_B + (size_t)tp*128 + half*2;
        #pragma unroll
        for (int q = 0; q < 4; q++) {
            float w0 = Wout[(size_t)(2*q)  *VOCAB + v];
            float w1 = Wout[(size_t)(2*q+1)*VOCAB + v];
            float w2 = Wout[(size_t)(2*q+8)*VOCAB + v];
            float w3 = Wout[(size_t)(2*q+9)*VOCAB + v];
            bp[(g*4+q)*4 + 0] = pack_bf16(w0, w1);
            bp[(g*4+q)*4 + 1] = pack_bf16(w2, w3);
        }
        return;
    }

    if (bx >= 126) {
        // ---- pre path: pairs [4i .. 4i+3], i = bx-126 ----
        int i = bx - 126;
        int pair = i*4 + (tid >> 6);   // 0..127
        int dir = pair >> 6, t = pair & 63, b = tid & 63;
        int gid = (dir*SEQ + t)*BATCH + b;
        if (gid < NROWS) g_sum[gid] = 0.f;

        const float* Wz = dir ? Wz2 : Wz1;
        const float* Wr = dir ? Wr2 : Wr1;
        const float* Wh = dir ? Wh2 : Wh1;
        float az = (dir ? bz2 : bz1)[0];
        float ar = (dir ? br2 : br1)[0];
        const float* bh = dir ? bh2 : bh1;
        float ah[8];
        #pragma unroll
        for (int j = 0; j < 8; j++) ah[j] = bh[j];

        int idx = x[t*BATCH + b];
        const float* e = emb + (size_t)idx * EMB;
        float ev[32];
        #pragma unroll
        for (int k = 0; k < 8; k++) {
            float4 v4 = ((const float4*)e)[k];
            ev[4*k+0] = v4.x; ev[4*k+1] = v4.y; ev[4*k+2] = v4.z; ev[4*k+3] = v4.w;
        }
        #pragma unroll
        for (int k = 0; k < 32; k++) {
            float evk = ev[k];
            az += evk * Wz[8 + k];
            ar += evk * Wr[8 + k];
            #pragma unroll
            for (int j = 0; j < 8; j++) ah[j] += evk * Wh[(8 + k)*8 + j];
        }
        float* Ab = g_A + (size_t)((dir*SEQ + t)*10)*BATCH + b;
        Ab[0] = az;
        Ab[BATCH] = ar;
        #pragma unroll
        for (int j = 0; j < 8; j++) Ab[(2 + j)*BATCH] = ah[j];

        __threadfence();
        __syncthreads();
        if (tid == 0)
            asm volatile("st.global.release.gpu.b32 [%0], %1;"
                         :: "l"(&g_pre_flag[i]), "r"(1) : "memory");
        return;
    }

    // ---- block 0: serial GRU, per-group flag waits ----
    if (tid >= 128) return;
    int dir = tid >> 6, b = tid & 63;
    const float* Wz = dir ? Wz2 : Wz1;
    const float* Wr = dir ? Wr2 : Wr1;
    const float* Wh = dir ? Wh2 : Wh1;

    float wz[8], wr[8], wh[64];
    #pragma unroll
    for (int i = 0; i < 8; i++) { wz[i] = Wz[i]; wr[i] = Wr[i]; }
    #pragma unroll
    for (int i = 0; i < 64; i++) wh[i] = Wh[i];

    float h[8];
    #pragma unroll
    for (int j = 0; j < 8; j++) h[j] = 0.f;

    float a[10];
    for (int grp = 0; grp < 16; ++grp) {
        int fidx = dir ? (31 - grp) : grp;
        // all threads of a warp share dir AND step -> same flag; poll + syncwarp
        int f;
        do {
            asm volatile("ld.global.acquire.gpu.b32 %0, [%1];"
                         : "=r"(f) : "l"(&g_pre_flag[fidx]) : "memory");
            if (!f) __nanosleep(60);
        } while (!f);
        __syncwarp();

        // load A for first step of group
        {
            int time0 = dir ? (63 - grp*4) : grp*4;
            const float* A = g_A + (size_t)((dir*SEQ + time0)*10)*BATCH + b;
            #pragma unroll
            for (int i = 0; i < 10; i++) a[i] = A[i*BATCH];
        }
        #pragma unroll
        for (int s = 0; s < 4; ++s) {
            int step = grp*4 + s;
            int time = dir ? (63 - step) : step;

            // prefetch next step's A while computing (within group)
            float an[10];
            if (s < 3) {
                int ntime = dir ? (time - 1) : (time + 1);
                const float* A = g_A + (size_t)((dir*SEQ + ntime)*10)*BATCH + b;
                #pragma unroll
                for (int i = 0; i < 10; i++) an[i] = A[i*BATCH];
            }

            float* gh = g_h + (size_t)(time*BATCH + b)*16 + dir*8;
            ((float4*)gh)[0] = make_float4(h[0], h[1], h[2], h[3]);
            ((float4*)gh)[1] = make_float4(h[4], h[5], h[6], h[7]);

            float zi = a[0], ri = a[1];
            #pragma unroll
            for (int i = 0; i < 8; i++) { zi += h[i]*wz[i]; ri += h[i]*wr[i]; }
            float z = sigmoid_fast(zi);
            float r = sigmoid_fast(ri);
            float rh[8];
            #pragma unroll
            for (int i = 0; i < 8; i++) rh[i] = r * h[i];
            float hc[8];
            #pragma unroll
            for (int j = 0; j < 8; j++) {
                float s2 = a[2 + j];
                #pragma unroll
                for (int i = 0; i < 8; i++) s2 += rh[i] * wh[i*8 + j];
                hc[j] = tanh_fast(s2);
            }
            #pragma unroll
            for (int j = 0; j < 8; j++) h[j] += z * (hc[j] - h[j]);

            if (s < 3) {
                #pragma unroll
                for (int i = 0; i < 10; i++) a[i] = an[i];
            }
        }
    }
    // all 4 GRU warps done -> reset flags for the next graph replay
    asm volatile("bar.sync 1, 128;" ::: "memory");
    if (tid < 32) g_pre_flag[tid] = 0;
}

// ---------------------------------------------------------------------------
// Sum pass — R13 measured form (A and bias pre-scaled by log2e; 2 MMAs/tile).
// ---------------------------------------------------------------------------
__global__ __launch_bounds__(256) void k_mma_sum(const float* __restrict__ bout)
{
    __shared__ __align__(16) float sb[256];
    int tid = threadIdx.x, lane = tid & 31, warp = tid >> 5;
    int mw = warp & 3, nw = warp >> 2;
    int n0 = blockIdx.x*256;
    sb[tid] = bout[n0 + tid] * LOG2E;
    __syncthreads();

    int q = lane & 3, g = lane >> 2;
    int r0 = blockIdx.y*64 + mw*16 + g;
    unsigned ahi[4], alo[4];
    build_a(r0, q, LOG2E, ahi, alo);

    const unsigned* Bp = g_B + ((size_t)(n0 >> 4) + nw*8)*128;
    const float* sbw = sb + nw*128;
    float accA = 0.f, accB = 0.f;

    #pragma unroll
    for (int tp = 0; tp < 8; tp++) {
        uint4 B = *(const uint4*)(Bp + tp*128 + lane*4);
        float2 bb0 = *(const float2*)(sbw + tp*16 + 2*q);
        float c0 = bb0.x, c1 = bb0.y, c2 = bb0.x, c3 = bb0.y;
        mma_bf16(c0,c1,c2,c3, ahi[0],ahi[1],ahi[2],ahi[3], B.x,B.y);
        mma_bf16(c0,c1,c2,c3, alo[0],alo[1],alo[2],alo[3], B.x,B.y);
        accA += ex2_fast(c0) + ex2_fast(c1);
        accB += ex2_fast(c2) + ex2_fast(c3);
        float2 bb1 = *(const float2*)(sbw + tp*16 + 8 + 2*q);
        float d0 = bb1.x, d1 = bb1.y, d2 = bb1.x, d3 = bb1.y;
        mma_bf16(d0,d1,d2,d3, ahi[0],ahi[1],ahi[2],ahi[3], B.z,B.w);
        mma_bf16(d0,d1,d2,d3, alo[0],alo[1],alo[2],alo[3], B.z,B.w);
        accA += ex2_fast(d0) + ex2_fast(d1);
        accB += ex2_fast(d2) + ex2_fast(d3);
    }
    accA += __shfl_xor_sync(0xffffffffu, accA, 1);
    accA += __shfl_xor_sync(0xffffffffu, accA, 2);
    accB += __shfl_xor_sync(0xffffffffu, accB, 1);
    accB += __shfl_xor_sync(0xffffffffu, accB, 2);
    if (q == 0) {
        atomicAdd(&g_sum[r0],     accA);
        atomicAdd(&g_sum[r0 + 8], accB);
    }
}

// ---------------------------------------------------------------------------
// Write pass — R13 single-buffer transposed epilogue (92.1us measured).
// ---------------------------------------------------------------------------
__global__ __launch_bounds__(256) void k_mma_write(
    const float* __restrict__ bout, float* __restrict__ out)
{
    __shared__ __align__(16) float sb[256];
    __shared__ float snls[64];
    __shared__ __align__(16) uint4 tsm[8][16*8];   // 16 KB

    int tid = threadIdx.x, lane = tid & 31, warp = tid >> 5;
    int mw = warp & 3, nw = warp >> 2;
    int n0 = blockIdx.x*256;
    sb[tid] = bout[n0 + tid];
    if (tid < 64) snls[tid] = -__logf(g_sum[blockIdx.y*64 + tid]);
    __syncthreads();

    int q = lane & 3, g = lane >> 2;
    int rowbase = blockIdx.y*64 + mw*16;
    int r0 = rowbase + g;
    unsigned ahi[4], alo[4];
    build_a(r0, q, 1.0f, ahi, alo);
    float nlsA = snls[mw*16 + g], nlsB = snls[mw*16 + g + 8];

    const unsigned* Bp = g_B + ((size_t)(n0 >> 4) + nw*8)*128;
    const float* sbw = sb + nw*128;
    float* tw = (float*)tsm[warp];
    int colbase = n0 + nw*128;
    int h = q & 1;

    #pragma unroll
    for (int G = 0; G < 4; G++) {
        #pragma unroll
        for (int tpp = 0; tpp < 2; tpp++) {
            int tp = G*2 + tpp;
            uint4 B = *(const uint4*)(Bp + tp*128 + lane*4);
            #pragma unroll
            for (int hf = 0; hf < 2; hf++) {
                int t = tp*2 + hf;
                int tt = tpp*2 + hf;
                unsigned b0 = hf ? B.z : B.x;
                unsigned b1 = hf ? B.w : B.y;
                float2 bb = *(const float2*)(sbw + t*8 + 2*q);
                float c0 = bb.x, c1 = bb.y, c2 = bb.x, c3 = bb.y;
                mma_bf16(c0,c1,c2,c3, ahi[0],ahi[1],ahi[2],ahi[3], b0,b1);
                mma_bf16(c0,c1,c2,c3, alo[0],alo[1],alo[2],alo[3], b0,b1);
                int Gl = tt*2 + (q >> 1);
                int pa = Gl ^ (g & 7);
                int pb = Gl ^ ((g + 8) & 7);
                *(float2*)(tw + (g*8 + pa)*4 + h*2)     = make_float2(c0 + nlsA, c1 + nlsA);
                *(float2*)(tw + ((g+8)*8 + pb)*4 + h*2) = make_float2(c2 + nlsB, c3 + nlsB);
            }
        }
        __syncwarp();
        #pragma unroll
        for (int i = 0; i < 4; i++) {
            int r = i*4 + (lane >> 3);
            int k = lane & 7;
            int p = k ^ (r & 7);
            uint4 vv = tsm[warp][r*8 + p];
            float* pd = out + (size_t)(rowbase + r)*VOCAB + colbase + G*32 + k*4;
            asm volatile("st.global.cs.v4.b32 [%0], {%1, %2, %3, %4};"
                         :: "l"(pd), "r"(vv.x), "r"(vv.y), "r"(vv.z), "r"(vv.w) : "memory");
        }
        __syncwarp();
    }
}

// ---------------------------------------------------------------------------
extern "C" void kernel_launch(void* const* d_in, const int* in_sizes, int n_in,
                              void* d_out, int out_size)
{
    const int*   x    = (const int*)  d_in[0];
    const float* emb  = (const float*)d_in[1];
    const float* Wz1  = (const float*)d_in[2];  const float* bz1 = (const float*)d_in[3];
    const float* Wr1  = (const float*)d_in[4];  const float* br1 = (const float*)d_in[5];
    const float* Wh1  = (const float*)d_in[6];  const float* bh1 = (const float*)d_in[7];
    const float* Wz2  = (const float*)d_in[8];  const float* bz2 = (const float*)d_in[9];
    const float* Wr2  = (const float*)d_in[10]; const float* br2 = (const float*)d_in[11];
    const float* Wh2  = (const float*)d_in[12]; const float* bh2 = (const float*)d_in[13];
    const float* Wout = (const float*)d_in[14]; const float* bout= (const float*)d_in[15];
    float* out = (float*)d_out;

    k_front<<<158, 256>>>(Wout, x, emb, Wz1, bz1, Wr1, br1, Wh1, bh1,
                          Wz2, bz2, Wr2, br2, Wh2, bh2);
    k_mma_sum  <<<dim3(VOCAB/256, NROWS/64), 256>>>(bout);
    k_mma_write<<<dim3(VOCAB/256, NROWS/64), 256>>>(bout, out);
}